// round 9
// baseline (speedup 1.0000x reference)
#include <cuda_runtime.h>
#include <math.h>
#include <stdint.h>
#include <string.h>

// ---------------------------------------------------------------------------
// Problem constants
//   inputs [2048, 84, 84, 4] NHWC fp32
//   conv 3x3 s2 SAME x4 (ELU), channels 4->32->32->32->32
//   84 -> 42 -> 21 -> 11 -> 6   (FEAT = 6*6*32 = 1152)
//   LSTM size 256 over TL=64 steps, NT=32 trajectories, forget_bias=1
//   FC 256 -> 18
// ---------------------------------------------------------------------------

#define NIMG   2048
#define NT     32
#define TL     64
#define FEAT   1152
#define HID    256
#define NOUT   18

typedef unsigned long long u64;

// ---------------- packed f32x2 helpers (FFMA2: PTX-only pattern) -----------
__device__ __forceinline__ u64 bcast2(float x) {
    u64 d; asm("mov.b64 %0, {%1, %1};" : "=l"(d) : "f"(x)); return d;
}
__device__ __forceinline__ u64 pack2(float a, float b) {
    u64 d; asm("mov.b64 %0, {%1, %2};" : "=l"(d) : "f"(a), "f"(b)); return d;
}
__device__ __forceinline__ float2 unpack2(u64 v) {
    float2 r; asm("mov.b64 {%0, %1}, %2;" : "=f"(r.x), "=f"(r.y) : "l"(v)); return r;
}
__device__ __forceinline__ void fma2(u64& d, u64 a, u64 b) {
    asm("fma.rn.f32x2 %0, %1, %2, %0;" : "+l"(d) : "l"(a), "l"(b));
}

__device__ __forceinline__ float elu_(float v) { return v > 0.f ? v : (__expf(v) - 1.f); }

// ------------------------- device scratch (no cudaMalloc allowed) ----------
__device__ float g_c1[(size_t)NIMG * 42 * 42 * 32];   // 462 MB
__device__ float g_c2[(size_t)NIMG * 21 * 21 * 32];   // 116 MB
__device__ float g_c3[(size_t)NIMG * 11 * 11 * 32];   //  32 MB
__device__ float g_c4[(size_t)NIMG * 6 * 6 * 32];     //   9 MB
__device__ float g_xg[(size_t)NIMG * 1024];           //   8 MB  x@Wx + b
__device__ float g_whr[HID * HID * 4];                //   1 MB  Wh interleaved

// ---------------------------------------------------------------------------
// Wh reorder: whr[(k*256 + t)*4 + g] = lstm_w[(1152+k)*1024 + g*256 + t]
// ---------------------------------------------------------------------------
__global__ void reorder_wh_k(const float* __restrict__ lw, float* __restrict__ whr)
{
    const int k = blockIdx.x;     // 0..255  (h input dim)
    const int t = threadIdx.x;    // 0..255  (hidden index)
    const float* row = lw + (size_t)(FEAT + k) * 1024;
    float4 v;
    v.x = row[t];          // i
    v.y = row[256 + t];    // j
    v.z = row[512 + t];    // f
    v.w = row[768 + t];    // o
    *(float4*)(whr + ((size_t)k * 256 + t) * 4) = v;
}

// ---------------------------------------------------------------------------
// conv1 v4: Cin=4 -> Cout=32, 84x84 -> 42x42, pad_begin=0 (SAME pads at end).
// TOX=4: small per-thread tile -> low regs -> high TLP (22 warps/SM).
// 352 threads = 8 co-groups x 11 ox-tiles x 4 rows. One image per block.
// ---------------------------------------------------------------------------
__global__ void __launch_bounds__(352, 2)
conv1_v4(const float* __restrict__ in, const float* __restrict__ w,
         const float* __restrict__ bias, float* __restrict__ out)
{
    __shared__ __align__(16) float sw[9 * 4 * 32];    // [kpos][ci][co]
    const int tid = threadIdx.x;
    if (tid < 288) *(float4*)(sw + tid * 4) = *(const float4*)(w + tid * 4);
    __syncthreads();

    const int cg   = tid & 7;
    const int rest = tid >> 3;
    const int oxg  = rest % 11;
    const int ry   = rest / 11;
    const int oy   = blockIdx.x * 4 + ry;             // grid.x=11 -> 44 rows, guard
    const int n    = blockIdx.y;
    const int co0  = cg * 4;
    const int ox0  = oxg * 4;                          // 0..40
    if (oy >= 42) return;

    u64 aL[4], aH[4];
    const u64 bL = pack2(bias[co0],     bias[co0 + 1]);
    const u64 bH = pack2(bias[co0 + 2], bias[co0 + 3]);
#pragma unroll
    for (int i = 0; i < 4; i++) { aL[i] = bL; aH[i] = bH; }

#pragma unroll 1
    for (int ky = 0; ky < 3; ky++) {
        const int iy = oy * 2 + ky;
        if (iy >= 84) continue;
        const float* inr = in + ((size_t)(n * 84 + iy) * 84) * 4;
#pragma unroll
        for (int kx = 0; kx < 3; kx++) {
            const float* swk = sw + ((ky * 3 + kx) * 4) * 32 + co0;
            const ulonglong2 w0 = *(const ulonglong2*)(swk);
            const ulonglong2 w1 = *(const ulonglong2*)(swk + 32);
            const ulonglong2 w2 = *(const ulonglong2*)(swk + 64);
            const ulonglong2 w3 = *(const ulonglong2*)(swk + 96);
#pragma unroll
            for (int i = 0; i < 4; i++) {
                const int ix = (ox0 + i) * 2 + kx;
                if (ix < 84) {
                    const float4 x = *(const float4*)(inr + (size_t)ix * 4);
                    u64 xb;
                    xb = bcast2(x.x); fma2(aL[i], xb, w0.x); fma2(aH[i], xb, w0.y);
                    xb = bcast2(x.y); fma2(aL[i], xb, w1.x); fma2(aH[i], xb, w1.y);
                    xb = bcast2(x.z); fma2(aL[i], xb, w2.x); fma2(aH[i], xb, w2.y);
                    xb = bcast2(x.w); fma2(aL[i], xb, w3.x); fma2(aH[i], xb, w3.y);
                }
            }
        }
    }
    float* outr = out + ((size_t)(n * 42 + oy) * 42) * 32 + co0;
#pragma unroll
    for (int i = 0; i < 4; i++) {
        const int ox = ox0 + i;
        if (ox < 42) {
            const float2 lo = unpack2(aL[i]), hi = unpack2(aH[i]);
            float4 v;
            v.x = elu_(lo.x); v.y = elu_(lo.y); v.z = elu_(hi.x); v.w = elu_(hi.y);
            *(float4*)(outr + (size_t)ox * 32) = v;
        }
    }
}

// ---------------------------------------------------------------------------
// convN v4: Cin=32 -> Cout=32, f32x2 over co pairs, TOX=3.
// Small per-thread tile (12 acc u64) -> natural reg footprint ~90 fits the
// BLK-blocks/SM cap WITHOUT spilling (R7 lesson: cap without shrinking tile
// => spills; R8 lesson: big tile at 2 blocks => latency-bound at 12 warps).
// ---------------------------------------------------------------------------
template <int IH, int IW, int OH, int OW, int PAD, int TOX, int OXT, int ROWS,
          int IPB, int BLK>
__global__ void __launch_bounds__(8 * OXT * ROWS * IPB, BLK)
conv32_v4(const float* __restrict__ in, const float* __restrict__ w,
          const float* __restrict__ bias, float* __restrict__ out)
{
    __shared__ __align__(16) float sw[9 * 32 * 32];   // [kpos][ci][co] = 36 KB
    const int tid = threadIdx.x;
    const int NTH = 8 * OXT * ROWS * IPB;
    for (int i = tid * 4; i < 9 * 32 * 32; i += NTH * 4)
        *(float4*)(sw + i) = *(const float4*)(w + i);
    __syncthreads();

    const int cg  = tid & 7;
    int rest      = tid >> 3;
    const int oxg = rest % OXT;  rest /= OXT;
    const int ry  = rest % ROWS;
    const int img = rest / ROWS;
    const int co0 = cg * 4;
    const int ox0 = oxg * TOX;
    const int oy  = blockIdx.x * ROWS + ry;
    const int n   = blockIdx.y * IPB + img;
    if (oy >= OH) return;

    u64 aL[TOX], aH[TOX];
    const u64 bL = pack2(bias[co0],     bias[co0 + 1]);
    const u64 bH = pack2(bias[co0 + 2], bias[co0 + 3]);
#pragma unroll
    for (int i = 0; i < TOX; i++) { aL[i] = bL; aH[i] = bH; }

#pragma unroll 1
    for (int ky = 0; ky < 3; ky++) {
        const int iy = oy * 2 + ky - PAD;
        if (iy < 0 || iy >= IH) continue;
        const float* inr = in + ((size_t)(n * IH + iy) * IW) * 32;
#pragma unroll
        for (int kx = 0; kx < 3; kx++) {
            const float* swk = sw + ((ky * 3 + kx) * 32) * 32 + co0;
#pragma unroll
            for (int c4 = 0; c4 < 32; c4 += 4) {
                const ulonglong2 w0 = *(const ulonglong2*)(swk + (c4 + 0) * 32);
                const ulonglong2 w1 = *(const ulonglong2*)(swk + (c4 + 1) * 32);
                const ulonglong2 w2 = *(const ulonglong2*)(swk + (c4 + 2) * 32);
                const ulonglong2 w3 = *(const ulonglong2*)(swk + (c4 + 3) * 32);
#pragma unroll
                for (int i = 0; i < TOX; i++) {
                    const int ix = (ox0 + i) * 2 + kx - PAD;
                    if (ix >= 0 && ix < IW) {
                        const float4 x = *(const float4*)(inr + (size_t)ix * 32 + c4);
                        u64 xb;
                        xb = bcast2(x.x); fma2(aL[i], xb, w0.x); fma2(aH[i], xb, w0.y);
                        xb = bcast2(x.y); fma2(aL[i], xb, w1.x); fma2(aH[i], xb, w1.y);
                        xb = bcast2(x.z); fma2(aL[i], xb, w2.x); fma2(aH[i], xb, w2.y);
                        xb = bcast2(x.w); fma2(aL[i], xb, w3.x); fma2(aH[i], xb, w3.y);
                    }
                }
            }
        }
    }
    float* outr = out + ((size_t)(n * OH + oy) * OW) * 32 + co0;
#pragma unroll
    for (int i = 0; i < TOX; i++) {
        if (ox0 + i < OW) {
            const float2 lo = unpack2(aL[i]), hi = unpack2(aH[i]);
            float4 v;
            v.x = elu_(lo.x); v.y = elu_(lo.y); v.z = elu_(hi.x); v.w = elu_(hi.y);
            *(float4*)(outr + (size_t)(ox0 + i) * 32) = v;
        }
    }
}

// ---------------------------------------------------------------------------
// SGEMM: xg[2048,1024] = c4[2048,1152] @ lstm_w[0:1152, 0:1024] + lstm_b
// 128x128x8 tiling, 256 threads, 8x8 micro-tile as f32x2 pairs over columns.
// ---------------------------------------------------------------------------
__global__ void __launch_bounds__(256, 2)
sgemm_xg_v2(const float* __restrict__ A, const float* __restrict__ B,
            const float* __restrict__ bias, float* __restrict__ C)
{
    __shared__ __align__(16) float As[8][128];
    __shared__ __align__(16) float Bs[8][128];
    const int bx  = blockIdx.x;   // 0..7   (N tiles)
    const int by  = blockIdx.y;   // 0..15  (M tiles)
    const int tid = threadIdx.x;
    const int tr  = (tid / 16) * 8;
    const int tc  = (tid % 16) * 8;

    u64 acc[8][4];
#pragma unroll
    for (int i = 0; i < 8; i++)
#pragma unroll
        for (int j = 0; j < 4; j++) acc[i][j] = 0ull;

    const int ar = tid >> 1,  ac = (tid & 1) * 4;
    const int br = tid >> 5,  bc = (tid & 31) * 4;
    const float* Aptr = A + (size_t)(by * 128 + ar) * FEAT + ac;
    const float* Bptr = B + (size_t)br * 1024 + bx * 128 + bc;

    for (int k0 = 0; k0 < FEAT; k0 += 8) {
        const float4 av = *(const float4*)(Aptr + k0);
        As[ac + 0][ar] = av.x; As[ac + 1][ar] = av.y;
        As[ac + 2][ar] = av.z; As[ac + 3][ar] = av.w;
        *(float4*)&Bs[br][bc] = *(const float4*)(Bptr + (size_t)k0 * 1024);
        __syncthreads();
#pragma unroll
        for (int kk = 0; kk < 8; kk++) {
            const float4 a0 = *(const float4*)&As[kk][tr];
            const float4 a1 = *(const float4*)&As[kk][tr + 4];
            const ulonglong2 b0 = *(const ulonglong2*)&Bs[kk][tc];
            const ulonglong2 b1 = *(const ulonglong2*)&Bs[kk][tc + 4];
            const float a[8] = {a0.x, a0.y, a0.z, a0.w, a1.x, a1.y, a1.z, a1.w};
#pragma unroll
            for (int i = 0; i < 8; i++) {
                const u64 ab = bcast2(a[i]);
                fma2(acc[i][0], ab, b0.x);
                fma2(acc[i][1], ab, b0.y);
                fma2(acc[i][2], ab, b1.x);
                fma2(acc[i][3], ab, b1.y);
            }
        }
        __syncthreads();
    }

#pragma unroll
    for (int i = 0; i < 8; i++) {
        const int row = by * 128 + tr + i;
        float* crow = C + (size_t)row * 1024 + bx * 128 + tc;
#pragma unroll
        for (int j = 0; j < 2; j++) {
            const float2 p0 = unpack2(acc[i][j * 2 + 0]);
            const float2 p1 = unpack2(acc[i][j * 2 + 1]);
            float4 v;
            v.x = p0.x + bias[bx * 128 + tc + j * 4 + 0];
            v.y = p0.y + bias[bx * 128 + tc + j * 4 + 1];
            v.z = p1.x + bias[bx * 128 + tc + j * 4 + 2];
            v.w = p1.y + bias[bx * 128 + tc + j * 4 + 3];
            *(float4*)(crow + j * 4) = v;
        }
    }
}

// ---------------------------------------------------------------------------
// Fused LSTM recurrence + FC. One persistent block per trajectory (32 blocks),
// 256 threads = hidden size. Thread t owns c[t] and accumulates gate pairs
// (i,j) and (f,o) as f32x2 with dual chains. h lives in SMEM; 18-col FC head
// runs in warps 0..5 each step, straight to d_out.
// ---------------------------------------------------------------------------
__device__ __forceinline__ float sigmoidf_(float x) { return 1.f / (1.f + expf(-x)); }

__global__ void __launch_bounds__(256)
lstm_fused_v2(const float* __restrict__ xg, const float* __restrict__ whr,
              const float* __restrict__ fcw, const float* __restrict__ fcb,
              const float* __restrict__ c0, const float* __restrict__ h0,
              float* __restrict__ out)
{
    const int n   = blockIdx.x;    // trajectory
    const int tid = threadIdx.x;   // hidden index
    __shared__ float sh[HID];

    float c = c0[(size_t)n * HID + tid];
    sh[tid] = h0[(size_t)n * HID + tid];
    __syncthreads();

    const int wrp = tid >> 5, lane = tid & 31;

    for (int t = 0; t < TL; t++) {
        const float* xrow = xg + (size_t)(n * TL + t) * 1024;
        u64 gij0 = pack2(xrow[tid],       xrow[256 + tid]), gij1 = 0ull;
        u64 gfo0 = pack2(xrow[512 + tid], xrow[768 + tid]), gfo1 = 0ull;

#pragma unroll 4
        for (int k = 0; k < HID; k += 2) {
            const u64 hb0 = bcast2(sh[k]);
            const ulonglong2 w0 = *(const ulonglong2*)(whr + ((size_t)k * HID + tid) * 4);
            fma2(gij0, hb0, w0.x); fma2(gfo0, hb0, w0.y);
            const u64 hb1 = bcast2(sh[k + 1]);
            const ulonglong2 w1 = *(const ulonglong2*)(whr + ((size_t)(k + 1) * HID + tid) * 4);
            fma2(gij1, hb1, w1.x); fma2(gfo1, hb1, w1.y);
        }
        const float2 ij0 = unpack2(gij0), ij1 = unpack2(gij1);
        const float2 fo0 = unpack2(gfo0), fo1 = unpack2(gfo1);
        const float gi = ij0.x + ij1.x, gj = ij0.y + ij1.y;
        const float gf = fo0.x + fo1.x, go = fo0.y + fo1.y;

        const float nc = c * sigmoidf_(gf + 1.f) + sigmoidf_(gi) * tanhf(gj);
        const float nh = tanhf(nc) * sigmoidf_(go);
        c = nc;

        __syncthreads();
        sh[tid] = nh;
        __syncthreads();

        // FC head: 18 columns, warps 0..5 take 3 columns each
        if (wrp < 6) {
#pragma unroll
            for (int cc = 0; cc < 3; cc++) {
                const int col = wrp * 3 + cc;
                float s = 0.f;
#pragma unroll
                for (int k = lane; k < HID; k += 32) s += sh[k] * fcw[(size_t)k * NOUT + col];
#pragma unroll
                for (int off = 16; off; off >>= 1) s += __shfl_down_sync(0xffffffffu, s, off);
                if (lane == 0)
                    out[(size_t)(n * TL + t) * NOUT + col] = s + fcb[col];
            }
        }
    }
}

// ---------------------------------------------------------------------------
// Launch
// ---------------------------------------------------------------------------
extern "C" void kernel_launch(void* const* d_in, const int* in_sizes, int n_in,
                              void* d_out, int out_size)
{
    (void)in_sizes; (void)n_in; (void)out_size;
    const float* inp = (const float*)d_in[0];
    const float* w1  = (const float*)d_in[1];
    const float* b1  = (const float*)d_in[2];
    const float* w2  = (const float*)d_in[3];
    const float* b2  = (const float*)d_in[4];
    const float* w3  = (const float*)d_in[5];
    const float* b3  = (const float*)d_in[6];
    const float* w4  = (const float*)d_in[7];
    const float* b4  = (const float*)d_in[8];
    const float* lw  = (const float*)d_in[9];
    const float* lb  = (const float*)d_in[10];
    const float* fw  = (const float*)d_in[11];
    const float* fb  = (const float*)d_in[12];
    const float* c0  = (const float*)d_in[13];
    const float* h0  = (const float*)d_in[14];
    float* out = (float*)d_out;

    float *c1, *c2, *c3, *c4, *xg, *whr;
    cudaGetSymbolAddress((void**)&c1,  g_c1);
    cudaGetSymbolAddress((void**)&c2,  g_c2);
    cudaGetSymbolAddress((void**)&c3,  g_c3);
    cudaGetSymbolAddress((void**)&c4,  g_c4);
    cudaGetSymbolAddress((void**)&xg,  g_xg);
    cudaGetSymbolAddress((void**)&whr, g_whr);

    // Wh reorder (independent of conv chain)
    reorder_wh_k<<<256, 256>>>(lw, whr);

    // conv stack — small per-thread tiles for high TLP without spills.
    // conv1: 84->42, TOX=4, 352 thr (8cg x 11oxt x 4rows), grid (11, 2048)
    conv1_v4<<<dim3(11, NIMG), 352>>>(inp, w1, b1, c1);
    // conv2: 42->21, TOX=3 OXT=7 ROWS=4 IPB=1 BLK=3 -> 224 thr, grid (6, 2048)
    conv32_v4<42, 42, 21, 21, 0, 3, 7, 4, 1, 3><<<dim3(6, NIMG), 224>>>(c1, w2, b2, c2);
    // conv3: 21->11, TOX=3 OXT=4 ROWS=6 IPB=1 BLK=3 -> 192 thr, grid (2, 2048)
    conv32_v4<21, 21, 11, 11, 1, 3, 4, 6, 1, 3><<<dim3(2, NIMG), 192>>>(c2, w3, b3, c3);
    // conv4: 11->6,  TOX=3 OXT=2 ROWS=6 IPB=2 BLK=3 -> 192 thr, grid (1, 1024)
    conv32_v4<11, 11,  6,  6, 1, 3, 2, 6, 2, 3><<<dim3(1, NIMG / 2), 192>>>(c3, w4, b4, c4);

    // time-parallel part of the LSTM input GEMM (+ bias), f32x2 micro-kernel
    sgemm_xg_v2<<<dim3(8, 16), 256>>>(c4, lw, lb, xg);

    // recurrence + FC head fused, one persistent block per trajectory
    lstm_fused_v2<<<NT, HID>>>(xg, whr, fw, fb, c0, h0, out);
}